// round 14
// baseline (speedup 1.0000x reference)
#include <cuda_runtime.h>
#include <cuda_bf16.h>
#include <cstdint>
#include <math.h>

// Problem shapes (fixed)
#define NX 4096
#define NY 16384
#define CX 128
#define CY 128
#define OD 256
#define KIN 256
#define BIGD 1e30f
#define W_EPS 1e-16f
#define LN_EPS 1e-5f

// Global scratch
__device__ __nv_bfloat16 g_Wh[OD * KIN];
__device__ __nv_bfloat16 g_Wl[OD * KIN];
__device__ float4 g_pos4[NX];                 // (x,y,z,|p|^2)

// ---------------------------------------------------------------------------
// Helpers (baseline PTX, valid for compute_100)
// ---------------------------------------------------------------------------
static __device__ __forceinline__ uint32_t smem_u32(const void* p) {
    uint32_t a;
    asm("{ .reg .u64 t; cvta.to.shared.u64 t, %1; cvt.u32.u64 %0, t; }"
        : "=r"(a) : "l"(p));
    return a;
}

static __device__ __forceinline__ void ldsm_x4(uint32_t addr, uint32_t* r) {
    asm volatile("ldmatrix.sync.aligned.m8n8.x4.shared.b16 {%0,%1,%2,%3}, [%4];"
                 : "=r"(r[0]), "=r"(r[1]), "=r"(r[2]), "=r"(r[3]) : "r"(addr));
}

static __device__ __forceinline__ void mma_bf16(float* d, const uint32_t* a,
                                                uint32_t b0, uint32_t b1) {
    asm volatile(
        "mma.sync.aligned.m16n8k16.row.col.f32.bf16.bf16.f32 "
        "{%0,%1,%2,%3},{%4,%5,%6,%7},{%8,%9},{%0,%1,%2,%3};"
        : "+f"(d[0]), "+f"(d[1]), "+f"(d[2]), "+f"(d[3])
        : "r"(a[0]), "r"(a[1]), "r"(a[2]), "r"(a[3]), "r"(b0), "r"(b1));
}

static __device__ __forceinline__ void cp_async16(uint32_t dst, const void* src) {
    asm volatile("cp.async.cg.shared.global [%0], [%1], 16;" :: "r"(dst), "l"(src));
}
static __device__ __forceinline__ void cp_commit() {
    asm volatile("cp.async.commit_group;" ::: "memory");
}
template <int N>
static __device__ __forceinline__ void cp_wait() {
    asm volatile("cp.async.wait_group %0;" :: "n"(N) : "memory");
}

// Fast hi/lo bf16 split of a float pair
static __device__ __forceinline__ void split_pair(float v0, float v1,
                                                  uint32_t& hp, uint32_t& lp) {
    uint32_t u0 = __float_as_uint(v0), u1 = __float_as_uint(v1);
    asm("prmt.b32 %0, %1, %2, 0x7632;" : "=r"(hp) : "r"(u0), "r"(u1));
    float h0 = __uint_as_float(u0 & 0xFFFF0000u);
    float h1 = __uint_as_float(u1 & 0xFFFF0000u);
    float l0 = v0 - h0, l1 = v1 - h1;
    asm("cvt.rn.bf16x2.f32 %0, %1, %2;" : "=r"(lp) : "f"(l1), "f"(l0));
}

// Exact branchless top-3 insert
static __device__ __forceinline__ void ins3(float d, int j,
                                            float& d0, float& d1, float& d2,
                                            int& i0, int& i1, int& i2) {
    bool lt0 = d < d0, lt1 = d < d1, lt2 = d < d2;
    d2 = lt1 ? d1 : (lt2 ? d : d2); i2 = lt1 ? i1 : (lt2 ? j : i2);
    d1 = lt0 ? d0 : (lt1 ? d : d1); i1 = lt0 ? i0 : (lt1 ? j : i1);
    d0 = lt0 ? d  : d0;             i0 = lt0 ? j  : i0;
}

// ---------------------------------------------------------------------------
// Kernel 0: W split + pos4 pack
// ---------------------------------------------------------------------------
__global__ __launch_bounds__(256)
void prep_small_kernel(const float* __restrict__ W,
                       const float* __restrict__ pos_x) {
    if (blockIdx.x < 32) {
        int base = blockIdx.x * (256 * 4) + threadIdx.x;
        uint32_t* wh = (uint32_t*)g_Wh;
        uint32_t* wl = (uint32_t*)g_Wl;
#pragma unroll
        for (int i = 0; i < 4; i++) {
            int p = base + i * 256;
            float2 v = *(const float2*)&W[p * 2];
            split_pair(v.x, v.y, wh[p], wl[p]);
        }
    } else {
        int idx = (int)(blockIdx.x - 32) * 256 + threadIdx.x;
        if (idx < NX) {
            float x = pos_x[idx * 3 + 0];
            float y = pos_x[idx * 3 + 1];
            float z = pos_x[idx * 3 + 2];
            g_pos4[idx] = make_float4(x, y, z, x * x + y * y + z * z);
        }
    }
}

// ---------------------------------------------------------------------------
// Kernel 1 (FUSED, half-tile pipeline):
//   Phase A : KNN half-0 (all 16 warps)
//   Pass 1  : GEMM half-0 (8 phases) with KNN half-1 chunks interleaved
//   LN h0   : (covers pass-2 B prefetch)
//   Pass 2  : GEMM half-1, B double-buffered over dead pos region
//   LN h1
// 128 CTAs x 512 thr; GEMM warps 2m x 8n, warp tile 32x32.
// SMEM (217088): A0@0 (hi 0 / lo 33792), A1@67584, B@135168 (hi/lo 20480),
//                POS@176128 (2560 float4). Stats overlay A0.
// ---------------------------------------------------------------------------
#define SROW 528
#define ALO_OFF 33792
#define A0B 0
#define A1B 67584
#define BB 135168
#define POSR 176128
#define BSTR 80
#define BLOF 20480
#define G_TOTAL 217088
#define MAXPTS 2560

__global__ __launch_bounds__(512, 1)
void fused_kernel(const float* __restrict__ pos_x,
                  const float* __restrict__ xfeat,
                  const int*   __restrict__ batch_x,
                  const float* __restrict__ pos_y,
                  const float* __restrict__ yfeat,
                  const int*   __restrict__ batch_y,
                  const float* __restrict__ gamma,
                  const float* __restrict__ beta,
                  float* __restrict__ out)
{
    extern __shared__ char smem[];
    const uint32_t sb = smem_u32(smem);
    __shared__ int sbounds[9];

    const int tid  = threadIdx.x;
    const int wid  = tid >> 5;
    const int lane = tid & 31;
    const int rowBase = blockIdx.x * 128;

    if (tid < 9) {
        int t = tid;
        int lo = 0, hi = NX;
        while (lo < hi) { int m = (lo + hi) >> 1; if (batch_x[m] < t) lo = m + 1; else hi = m; }
        sbounds[t] = lo;
    }
    __syncthreads();

    const int bmin = batch_y[rowBase];
    const int bmax = batch_y[rowBase + 127];
    const int s0   = sbounds[bmin];
    const int n    = sbounds[bmax + 1] - s0;
    const bool inSmem = (n <= MAXPTS);

    // ---- B phase loader ----
    auto load_B = [&](int p, uint32_t bb) {
        const int kof = p * 32;
#pragma unroll
        for (int i = 0; i < 2; i++) {
            int idx = tid + i * 512;
            int r = idx >> 2, kc = idx & 3;
            const size_t gs = (size_t)r * KIN + kof + kc * 8;
            uint32_t off = (uint32_t)(r * BSTR + kc * 16);
            cp_async16(bb + off, &g_Wh[gs]);
            cp_async16(bb + BLOF + off, &g_Wl[gs]);
        }
        cp_commit();
    };

    load_B(0, sb + BB);                      // prefetch B(0) during phase A

    // ---- stage pos4 segment ----
    if (inSmem) {
        for (int i = tid; i < n; i += 512)
            *(float4*)(smem + POSR + (uint32_t)i * 16) = g_pos4[s0 + i];
    }
    __syncthreads();

    // ---- row writer: interp + split into A buffer ----
    auto write_row = [&](uint32_t AHbase, int yi, int ylocHalf,
                         float d0, float d1, float d2, int i0, int i1, int i2) {
        const float w0 = 1.0f / fmaxf(d0, W_EPS);
        const float w1 = 1.0f / fmaxf(d1, W_EPS);
        const float w2 = 1.0f / fmaxf(d2, W_EPS);
        const float inv_wsum = 1.0f / (w0 + w1 + w2);
        const float* f0 = xfeat + (size_t)i0 * CX;
        const float* f1 = xfeat + (size_t)i1 * CX;
        const float* f2 = xfeat + (size_t)i2 * CX;
        const float* fy = yfeat + (size_t)yi * CY;
        const int c = lane * 4;
        float4 a0 = *(const float4*)&f0[c];
        float4 a1 = *(const float4*)&f1[c];
        float4 a2 = *(const float4*)&f2[c];
        float4 ay = *(const float4*)&fy[c];
        float v0 = (w0 * a0.x + w1 * a1.x + w2 * a2.x) * inv_wsum;
        float v1 = (w0 * a0.y + w1 * a1.y + w2 * a2.y) * inv_wsum;
        float v2 = (w0 * a0.z + w1 * a1.z + w2 * a2.z) * inv_wsum;
        float v3 = (w0 * a0.w + w1 * a1.w + w2 * a2.w) * inv_wsum;
        const uint32_t arow = AHbase + (uint32_t)(ylocHalf * SROW + lane * 8);
        uint2 hp, lp;
        split_pair(v0, v1, hp.x, lp.x);
        split_pair(v2, v3, hp.y, lp.y);
        *(uint2*)(smem + arow) = hp;
        *(uint2*)(smem + arow + ALO_OFF) = lp;
        split_pair(ay.x, ay.y, hp.x, lp.x);
        split_pair(ay.z, ay.w, hp.y, lp.y);
        *(uint2*)(smem + arow + 256) = hp;
        *(uint2*)(smem + arow + ALO_OFF + 256) = lp;
    };

    auto warp_merge = [&](float& d0, float& d1, float& d2,
                          int& i0, int& i1, int& i2) {
        for (int off = 16; off; off >>= 1) {
            float od0 = __shfl_xor_sync(0xffffffffu, d0, off);
            float od1 = __shfl_xor_sync(0xffffffffu, d1, off);
            float od2 = __shfl_xor_sync(0xffffffffu, d2, off);
            int   oi0 = __shfl_xor_sync(0xffffffffu, i0, off);
            int   oi1 = __shfl_xor_sync(0xffffffffu, i1, off);
            int   oi2 = __shfl_xor_sync(0xffffffffu, i2, off);
            ins3(od0, oi0, d0, d1, d2, i0, i1, i2);
            ins3(od1, oi1, d0, d1, d2, i0, i1, i2);
            ins3(od2, oi2, d0, d1, d2, i0, i1, i2);
        }
    };

    // full KNN for one query (used in phase A / fallback)
    auto knn_full = [&](uint32_t AHbase, int yi, int ylocHalf) {
        const float qx = pos_y[yi * 3 + 0];
        const float qy = pos_y[yi * 3 + 1];
        const float qz = pos_y[yi * 3 + 2];
        const float qn = qx * qx + qy * qy + qz * qz;
        const int b = batch_y[yi];
        const int s = sbounds[b], e = sbounds[b + 1];
        float dP0 = BIGD, dP1 = BIGD, dP2 = BIGD; int iP0 = 0, iP1 = 0, iP2 = 0;
        if (inSmem) {
            float dQ0 = BIGD, dQ1 = BIGD, dQ2 = BIGD; int iQ0 = 0, iQ1 = 0, iQ2 = 0;
            const int ls = s - s0, le = e - s0;
            int jl = ls + lane;
            for (; jl + 32 < le; jl += 64) {
                float4 p0 = *(const float4*)(smem + POSR + (uint32_t)jl * 16);
                float4 p1 = *(const float4*)(smem + POSR + (uint32_t)(jl + 32) * 16);
                float da = fmaxf(qn + p0.w - 2.0f * (qx * p0.x + qy * p0.y + qz * p0.z), 0.0f);
                float db = fmaxf(qn + p1.w - 2.0f * (qx * p1.x + qy * p1.y + qz * p1.z), 0.0f);
                ins3(da, s0 + jl,      dP0, dP1, dP2, iP0, iP1, iP2);
                ins3(db, s0 + jl + 32, dQ0, dQ1, dQ2, iQ0, iQ1, iQ2);
            }
            if (jl < le) {
                float4 p0 = *(const float4*)(smem + POSR + (uint32_t)jl * 16);
                float da = fmaxf(qn + p0.w - 2.0f * (qx * p0.x + qy * p0.y + qz * p0.z), 0.0f);
                ins3(da, s0 + jl, dP0, dP1, dP2, iP0, iP1, iP2);
            }
            ins3(dQ0, iQ0, dP0, dP1, dP2, iP0, iP1, iP2);
            ins3(dQ1, iQ1, dP0, dP1, dP2, iP0, iP1, iP2);
            ins3(dQ2, iQ2, dP0, dP1, dP2, iP0, iP1, iP2);
        } else {
            for (int j = s + lane; j < e; j += 32) {
                float4 p = g_pos4[j];
                float d = fmaxf(qn + p.w - 2.0f * (qx * p.x + qy * p.y + qz * p.z), 0.0f);
                ins3(d, j, dP0, dP1, dP2, iP0, iP1, iP2);
            }
        }
        warp_merge(dP0, dP1, dP2, iP0, iP1, iP2);
        write_row(AHbase, yi, ylocHalf, dP0, dP1, dP2, iP0, iP1, iP2);
    };

    // ---- PHASE A: KNN half-0 (rows 0..63), 4 queries per warp ----
    for (int q = 0; q < 4; q++)
        knn_full(A0B, rowBase + wid * 4 + q, wid * 4 + q);
    if (!inSmem) {                           // fallback: also do half-1 now
        for (int q = 0; q < 4; q++)
            knn_full(A1B, rowBase + 64 + wid * 4 + q, wid * 4 + q);
    }
    __syncthreads();

    // ---- GEMM per-lane constants ----
    const int g    = lane >> 2;
    const int tig  = lane & 3;
    const int mw   = (wid >> 3) * 32;      // warp row base within 64-row half
    const int nw   = wid & 7;              // warp col base = nw*32
    const int quad = lane >> 3;
    const int lrow = lane & 7;
    const int aRow  = (quad & 1) * 8 + lrow;
    const int aKoff = (quad >> 1) * 8;
    const int bRow  = ((lane >> 4) * 8) + lrow;
    const int bKoff = ((lane >> 3) & 1) * 8;
    const uint32_t offB = (uint32_t)((nw * 32 + bRow) * BSTR + bKoff * 2);
    const uint32_t aCol = (uint32_t)((mw + aRow) * SROW + aKoff * 2);

    float acc[2][4][4];
    auto acc_zero = [&]() {
#pragma unroll
        for (int mt = 0; mt < 2; mt++)
#pragma unroll
            for (int nt = 0; nt < 4; nt++)
#pragma unroll
                for (int j = 0; j < 4; j++) acc[mt][nt][j] = 0.f;
    };

    auto gemm_phase = [&](uint32_t AHbase, int p, uint32_t bb) {
        const uint32_t bB = bb + offB;
        const uint32_t aB = sb + AHbase + aCol + (uint32_t)(p * 64);
#pragma unroll
        for (int ks = 0; ks < 2; ks++) {
            const uint32_t kb = (uint32_t)(ks * 32);
            uint32_t Bh[8], Bl[8];
            ldsm_x4(bB + kb, Bh);
            ldsm_x4(bB + 1280 + kb, Bh + 4);
            ldsm_x4(bB + BLOF + kb, Bl);
            ldsm_x4(bB + BLOF + 1280 + kb, Bl + 4);
#pragma unroll
            for (int mt = 0; mt < 2; mt++) {
                uint32_t Ah[4], Al[4];
                const uint32_t aa = aB + (uint32_t)(mt * 16 * SROW) + kb;
                ldsm_x4(aa, Ah);
                ldsm_x4(aa + ALO_OFF, Al);
#pragma unroll
                for (int nt = 0; nt < 4; nt++)
                    mma_bf16(acc[mt][nt], Ah, Bh[2 * nt], Bh[2 * nt + 1]);
#pragma unroll
                for (int nt = 0; nt < 4; nt++)
                    mma_bf16(acc[mt][nt], Al, Bh[2 * nt], Bh[2 * nt + 1]);
#pragma unroll
                for (int nt = 0; nt < 4; nt++)
                    mma_bf16(acc[mt][nt], Ah, Bl[2 * nt], Bl[2 * nt + 1]);
            }
        }
    };

    // ---- LN + store for one half ----
    auto ln_store = [&](int halfBase) {
        float* sSum = (float*)(smem + A0B);    // overlay dead A0 region
        float* sSq  = sSum + 512;              // [64][8]
        float* sMu  = sSq + 512;
        float* sRs  = sMu + 64;
#pragma unroll
        for (int mt = 0; mt < 2; mt++)
#pragma unroll
            for (int half = 0; half < 2; half++) {
                float s = 0.f, q = 0.f;
#pragma unroll
                for (int nt = 0; nt < 4; nt++)
#pragma unroll
                    for (int j = 0; j < 2; j++) {
                        float v = acc[mt][nt][half * 2 + j];
                        s += v; q += v * v;
                    }
                s += __shfl_xor_sync(0xffffffffu, s, 1);
                q += __shfl_xor_sync(0xffffffffu, q, 1);
                s += __shfl_xor_sync(0xffffffffu, s, 2);
                q += __shfl_xor_sync(0xffffffffu, q, 2);
                if (tig == 0) {
                    int row = mw + mt * 16 + half * 8 + g;
                    sSum[row * 8 + nw] = s;
                    sSq[row * 8 + nw]  = q;
                }
            }
        __syncthreads();
        if (tid < 64) {
            float s = 0.f, q = 0.f;
#pragma unroll
            for (int i = 0; i < 8; i++) { s += sSum[tid * 8 + i]; q += sSq[tid * 8 + i]; }
            float mu = s * (1.0f / OD);
            float var = fmaxf(q * (1.0f / OD) - mu * mu, 0.0f);
            sMu[tid] = mu;
            sRs[tid] = rsqrtf(var + LN_EPS);
        }
        __syncthreads();
#pragma unroll
        for (int mt = 0; mt < 2; mt++)
#pragma unroll
            for (int half = 0; half < 2; half++) {
                int row = mw + mt * 16 + half * 8 + g;
                float mu = sMu[row];
                float rs = sRs[row];
                float* orow = out + (size_t)(rowBase + halfBase + row) * OD;
#pragma unroll
                for (int nt = 0; nt < 4; nt++) {
                    int col = nw * 32 + nt * 8 + tig * 2;
                    float2 gb0 = *(const float2*)&gamma[col];
                    float2 bb0 = *(const float2*)&beta[col];
                    float v0 = acc[mt][nt][half * 2 + 0];
                    float v1 = acc[mt][nt][half * 2 + 1];
                    float2 r2;
                    r2.x = fmaxf((v0 - mu) * rs * gb0.x + bb0.x, 0.0f);
                    r2.y = fmaxf((v1 - mu) * rs * gb0.y + bb0.y, 0.0f);
                    *(float2*)&orow[col] = r2;
                }
            }
        __syncthreads();
    };

    // ======================= PASS 1: half-0 GEMM + half-1 KNN ==============
    cp_wait<0>();
    __syncthreads();                         // B(0) ready
    acc_zero();

    // persistent KNN chunk state
    float kd0 = BIGD, kd1 = BIGD, kd2 = BIGD;
    int   ki0 = 0, ki1 = 0, ki2 = 0;
    int   kjl = 0, kcut = 0, kle = 0, kyi = 0, kyloc = 0;
    float kqx = 0.f, kqy = 0.f, kqz = 0.f, kqn = 0.f;

#pragma unroll 1
    for (int pp = 0; pp < 4; pp++) {
        // ---- even phase p = 2*pp ----
        {
            const int p = 2 * pp;
            gemm_phase(A0B, p, sb + BB);
            __syncthreads();                 // B(p) consumed
            load_B(p + 1, sb + BB);
            if (inSmem) {                    // init + first half of scan
                kyloc = wid * 4 + pp;
                kyi = rowBase + 64 + kyloc;
                kqx = pos_y[kyi * 3 + 0];
                kqy = pos_y[kyi * 3 + 1];
                kqz = pos_y[kyi * 3 + 2];
                kqn = kqx * kqx + kqy * kqy + kqz * kqz;
                const int b = batch_y[kyi];
                const int ls = sbounds[b] - s0;
                kle = sbounds[b + 1] - s0;
                kjl = ls + lane;
                kcut = ls + (((kle - ls) >> 1) & ~31);
                kd0 = BIGD; kd1 = BIGD; kd2 = BIGD;
                ki0 = 0; ki1 = 0; ki2 = 0;
                for (; kjl < kcut; kjl += 32) {
                    float4 pt = *(const float4*)(smem + POSR + (uint32_t)kjl * 16);
                    float d = fmaxf(kqn + pt.w - 2.0f * (kqx * pt.x + kqy * pt.y + kqz * pt.z), 0.0f);
                    ins3(d, s0 + kjl, kd0, kd1, kd2, ki0, ki1, ki2);
                }
            }
            cp_wait<0>();
            __syncthreads();                 // B(p+1) ready
        }
        // ---- odd phase p = 2*pp+1 ----
        {
            const int p = 2 * pp + 1;
            gemm_phase(A0B, p, sb + BB);
            __syncthreads();                 // B(p) consumed
            if (p < 7) load_B(p + 1, sb + BB);
            if (inSmem) {                    // finish scan + merge + write
                for (; kjl < kle; kjl += 32) {
                    float4 pt = *(const float4*)(smem + POSR + (uint32_t)kjl * 16);
                    float d = fmaxf(kqn + pt.w - 2.0f * (kqx * pt.x + kqy * pt.y + kqz * pt.z), 0.0f);
                    ins3(d, s0 + kjl, kd0, kd1, kd2, ki0, ki1, ki2);
                }
                warp_merge(kd0, kd1, kd2, ki0, ki1, ki2);
                write_row(A1B, kyi, kyloc, kd0, kd1, kd2, ki0, ki1, ki2);
            }
            if (p < 7) cp_wait<0>();
            __syncthreads();                 // B(p+1) ready / A1 visible
        }
    }

    // ---- LN + store half-0 (covers pass-2 B(0) prefetch) ----
    load_B(0, sb + BB);
    ln_store(0);
    cp_wait<0>();
    __syncthreads();

    // ======================= PASS 2: half-1 GEMM (double-buffered) =========
    acc_zero();
#pragma unroll 1
    for (int p = 0; p < 8; p++) {
        const uint32_t cur = (p & 1) ? (sb + POSR) : (sb + BB);
        if (p < 7) load_B(p + 1, (p & 1) ? (sb + BB) : (sb + POSR));
        gemm_phase(A1B, p, cur);
        if (p < 7) cp_wait<0>();
        __syncthreads();
    }
    ln_store(64);
}

// ---------------------------------------------------------------------------
extern "C" void kernel_launch(void* const* d_in, const int* in_sizes, int n_in,
                              void* d_out, int out_size)
{
    const float* pos_x   = (const float*)d_in[0];
    const float* xfeat   = (const float*)d_in[1];
    const int*   batch_x = (const int*)  d_in[2];
    const float* pos_y   = (const float*)d_in[3];
    const float* yfeat   = (const float*)d_in[4];
    const int*   batch_y = (const int*)  d_in[5];
    const float* W       = (const float*)d_in[6];
    const float* gamma   = (const float*)d_in[7];
    const float* beta    = (const float*)d_in[8];
    float* out = (float*)d_out;

    prep_small_kernel<<<48, 256>>>(W, pos_x);

    cudaFuncSetAttribute(fused_kernel,
                         cudaFuncAttributeMaxDynamicSharedMemorySize, G_TOTAL);
    fused_kernel<<<NY / 128, 512, G_TOTAL>>>(pos_x, xfeat, batch_x, pos_y,
                                             yfeat, batch_y, gamma, beta, out);
}